// round 13
// baseline (speedup 1.0000x reference)
#include <cuda_runtime.h>
#include <cuda_fp16.h>
#include <math.h>
#include <stdint.h>

#define N_ROIS 2000
#define MPAD   2048
#define IN_F   12544
#define REP    1024
#define NHEAD  512
#define NCLS   91
#define NC1    90
#define NPAD   2048
#define BBOX_CLIP_F 4.135166556742356f
#define MAXDET 100

// ======================= static scratch (no allocs) =======================
__device__ float gWhf[REP * NHEAD];
__device__ float gBiasH[NHEAD];
__device__ float gPart[2 * MPAD * REP];    // split-K partials for GEMM1
__device__ float gH1f[MPAD * REP];
__device__ float gH2f[MPAD * REP];
__device__ float g_comb[N_ROIS * NHEAD];
__device__ float g_scores[N_ROIS * NCLS];
__device__ unsigned long long g_surv[NC1 * MAXDET];
__device__ int g_snum[NC1];

// ======================= helpers =======================
__device__ __forceinline__ uint32_t s2u(const void* p) {
    uint32_t a;
    asm("{ .reg .u64 t; cvta.to.shared.u64 t, %1; cvt.u32.u64 %0, t; }" : "=r"(a) : "l"(p));
    return a;
}
__device__ __forceinline__ void ldm4(uint32_t* r, uint32_t addr) {
    asm volatile("ldmatrix.sync.aligned.m8n8.x4.shared.b16 {%0,%1,%2,%3}, [%4];"
                 : "=r"(r[0]), "=r"(r[1]), "=r"(r[2]), "=r"(r[3]) : "r"(addr));
}
__device__ __forceinline__ void ldm4t(uint32_t* r, uint32_t addr) {
    asm volatile("ldmatrix.sync.aligned.m8n8.x4.trans.shared.b16 {%0,%1,%2,%3}, [%4];"
                 : "=r"(r[0]), "=r"(r[1]), "=r"(r[2]), "=r"(r[3]) : "r"(addr));
}
__device__ __forceinline__ void mma_f16(float* d, const uint32_t* a, const uint32_t* b) {
    asm volatile(
        "mma.sync.aligned.m16n8k16.row.col.f32.f16.f16.f32 "
        "{%0,%1,%2,%3}, {%4,%5,%6,%7}, {%8,%9}, {%0,%1,%2,%3};"
        : "+f"(d[0]), "+f"(d[1]), "+f"(d[2]), "+f"(d[3])
        : "r"(a[0]), "r"(a[1]), "r"(a[2]), "r"(a[3]), "r"(b[0]), "r"(b[1]));
}
__device__ __forceinline__ void split2u(float x, __half& h, __half& l) {
    h = __float2half_rn(x);
    l = __float2half_rn(x - __half2float(h));
}
__device__ __forceinline__ uint32_t pack2(__half a, __half b) {
    __half2 t; t.x = a; t.y = b;
    return *reinterpret_cast<uint32_t*>(&t);
}
__device__ __forceinline__ void split8(const float4& v0, const float4& v1,
                                       uint4& hi, uint4& lo) {
    __half h0, l0, h1, l1, h2, l2, h3, l3, h4, l4, h5, l5, h6, l6, h7, l7;
    split2u(v0.x, h0, l0); split2u(v0.y, h1, l1);
    split2u(v0.z, h2, l2); split2u(v0.w, h3, l3);
    split2u(v1.x, h4, l4); split2u(v1.y, h5, l5);
    split2u(v1.z, h6, l6); split2u(v1.w, h7, l7);
    hi.x = pack2(h0, h1); hi.y = pack2(h2, h3);
    hi.z = pack2(h4, h5); hi.w = pack2(h6, h7);
    lo.x = pack2(l0, l1); lo.y = pack2(l2, l3);
    lo.z = pack2(l4, l5); lo.w = pack2(l6, l7);
}
__device__ __forceinline__ void decode_one(
    int n, int c, const float* __restrict__ P, float Wim, float Him,
    float& x1, float& y1, float& x2, float& y2)
{
    const float4 p = *reinterpret_cast<const float4*>(&P[n * 4]);
    const float pw = p.z - p.x;
    const float ph = p.w - p.y;
    const float pcx = p.x + 0.5f * pw;
    const float pcy = p.y + 0.5f * ph;
    const float4 r = *reinterpret_cast<const float4*>(&g_comb[(size_t)n * NHEAD + 92 + c * 4]);
    const float dx = r.x / 10.0f;
    const float dy = r.y / 10.0f;
    const float dw = fminf(r.z / 5.0f, BBOX_CLIP_F);
    const float dh = fminf(r.w / 5.0f, BBOX_CLIP_F);
    const float cx = dx * pw + pcx;
    const float cy = dy * ph + pcy;
    const float w = expf(dw) * pw;
    const float hh = expf(dh) * ph;
    x1 = fminf(fmaxf(cx - 0.5f * w, 0.f), Wim);
    y1 = fminf(fmaxf(cy - 0.5f * hh, 0.f), Him);
    x2 = fminf(fmaxf(cx + 0.5f * w, 0.f), Wim);
    y2 = fminf(fmaxf(cy + 0.5f * hh, 0.f), Him);
}

// ======================= tiny pre-pass =======================
__global__ void build_headW(const float* __restrict__ Wc, const float* __restrict__ Wr) {
    const int idx = blockIdx.x * 256 + threadIdx.x;
    const int k = idx >> 9;
    const int n = idx & (NHEAD - 1);
    float v = 0.f;
    if (n < NCLS) v = Wc[(size_t)k * NCLS + n];
    else if (n >= 92 && n < 92 + 4 * NCLS) v = Wr[(size_t)k * (4 * NCLS) + (n - 92)];
    gWhf[idx] = v;
}
__global__ void build_bias(const float* __restrict__ bc, const float* __restrict__ br) {
    const int c = blockIdx.x * 256 + threadIdx.x;
    if (c >= NHEAD) return;
    float v = 0.f;
    if (c < NCLS) v = bc[c];
    else if (c >= 92 && c < 92 + 4 * NCLS) v = br[c - 92];
    gBiasH[c] = v;
}

// ======================= WIDE split-K GEMM: 128M x 256N, 8 warps of 64x64 =======================
// Partial C (no bias/relu) written to part[z]. acc += Ah*Bh + Ah*Bl + Al*Bh.
#define STGW   49152           // A 16KB + B hi 16KB + B lo 16KB
#define SMEMW  (3 * STGW)

__global__ void __launch_bounds__(256, 1) hgemmW(
    const float* __restrict__ A, const float* __restrict__ B,
    int lda, int ldb, int Mreal, int kchunk,
    float* __restrict__ part)
{
    extern __shared__ __align__(16) char smem[];
    const uint32_t sb = s2u(smem);
    const int tid = threadIdx.x;
    const int lane = tid & 31, wid = tid >> 5;
    const int wm = wid >> 2, wn = wid & 3;          // 2 x 4 warps, tile 64x64
    const int bm = blockIdx.y * 128, bn = blockIdx.x * 256;
    const int kbeg = blockIdx.z * kchunk;
    const int niter = kchunk >> 5;
    float* C = part + (size_t)blockIdx.z * MPAD * REP;

    float acc[4][8][4];
#pragma unroll
    for (int m = 0; m < 4; ++m)
#pragma unroll
        for (int n = 0; n < 8; ++n)
#pragma unroll
            for (int e = 0; e < 4; ++e) acc[m][n][e] = 0.f;

    // A: 128 rows x 4 k8-chunks = 512 chunks, 2/thread
    // B: 32 krows x 32 n8-chunks = 1024 chunks, 4/thread
    auto loadStore = [&](int i) {
        char* st = smem + (size_t)(i % 3) * STGW;
        const int k0 = kbeg + i * 32;
        float4 av[2][2], bv[4][2];
#pragma unroll
        for (int j = 0; j < 2; ++j) {
            const int q = tid + 256 * j;
            const int row = q >> 2, kc = q & 3;
            const int gr = bm + row;
            if (gr < Mreal) {
                const float* p = A + (size_t)gr * lda + k0 + kc * 8;
                av[j][0] = *(const float4*)p;
                av[j][1] = *(const float4*)(p + 4);
            } else {
                av[j][0] = make_float4(0.f, 0.f, 0.f, 0.f);
                av[j][1] = av[j][0];
            }
        }
#pragma unroll
        for (int j = 0; j < 4; ++j) {
            const int q = tid + 256 * j;
            const int row = q >> 5, nc = q & 31;
            const float* p = B + (size_t)(k0 + row) * ldb + bn + nc * 8;
            bv[j][0] = *(const float4*)p;
            bv[j][1] = *(const float4*)(p + 4);
        }
#pragma unroll
        for (int j = 0; j < 2; ++j) {
            const int q = tid + 256 * j;
            const int row = q >> 2, kc = q & 3;
            uint4 hi, lo;
            split8(av[j][0], av[j][1], hi, lo);
            uint32_t relh = (uint32_t)(row * 128 + kc * 16);
            relh ^= (relh >> 3) & 0x70;
            uint32_t rell = (uint32_t)(row * 128 + 64 + kc * 16);
            rell ^= (rell >> 3) & 0x70;
            *(uint4*)(st + relh) = hi;
            *(uint4*)(st + rell) = lo;
        }
#pragma unroll
        for (int j = 0; j < 4; ++j) {
            const int q = tid + 256 * j;
            const int row = q >> 5, nc = q & 31;
            uint4 hi, lo;
            split8(bv[j][0], bv[j][1], hi, lo);
            uint32_t rel = (uint32_t)(row * 512 + nc * 16);
            rel ^= ((rel >> 9) & 7) << 4;
            *(uint4*)(st + 16384 + rel) = hi;
            *(uint4*)(st + 32768 + rel) = lo;
        }
    };

    auto compute = [&](int i) {
        const uint32_t ab = sb + (uint32_t)(i % 3) * STGW;
        const uint32_t bhi = ab + 16384;
        const uint32_t blo = ab + 32768;
#pragma unroll
        for (int kk = 0; kk < 2; ++kk) {
            uint32_t Af[4][4], Lf[4][4];
#pragma unroll
            for (int m = 0; m < 4; ++m) {
                const int row = wm * 64 + m * 16 + (lane & 15);
                const int colb = kk * 32 + ((lane >> 4) << 4);
                uint32_t r1 = (uint32_t)(row * 128 + colb);
                uint32_t r2 = (uint32_t)(row * 128 + 64 + colb);
                r1 ^= (r1 >> 3) & 0x70;
                r2 ^= (r2 >> 3) & 0x70;
                ldm4(Af[m], ab + r1);
                ldm4(Lf[m], ab + r2);
            }
#pragma unroll
            for (int p = 0; p < 4; ++p) {
                const int grp = lane >> 3, kr = lane & 7;
                const int kx = kk * 16 + (grp & 1) * 8 + kr;
                const int nb = wn * 64 + p * 16 + (grp >> 1) * 8;
                uint32_t rel = (uint32_t)(kx * 512 + nb * 2);
                rel ^= ((rel >> 9) & 7) << 4;
                uint32_t Bf[2][2], Mf[2][2];
                uint32_t t[4];
                ldm4t(t, bhi + rel);
                Bf[0][0] = t[0]; Bf[0][1] = t[1];
                Bf[1][0] = t[2]; Bf[1][1] = t[3];
                ldm4t(t, blo + rel);
                Mf[0][0] = t[0]; Mf[0][1] = t[1];
                Mf[1][0] = t[2]; Mf[1][1] = t[3];
#pragma unroll
                for (int m = 0; m < 4; ++m)
#pragma unroll
                    for (int j = 0; j < 2; ++j) {
                        mma_f16(acc[m][p * 2 + j], Af[m], Bf[j]);
                        mma_f16(acc[m][p * 2 + j], Af[m], Mf[j]);
                        mma_f16(acc[m][p * 2 + j], Lf[m], Bf[j]);
                    }
            }
        }
    };

    loadStore(0);
    if (niter > 1) { __syncthreads(); loadStore(1); }
    __syncthreads();
    for (int i = 0; i < niter; ++i) {
        compute(i);
        __syncthreads();
        if (i + 2 < niter) loadStore(i + 2);
        __syncthreads();
    }

    // epilogue: partial sums (no bias)
    const int rb = bm + wm * 64 + (lane >> 2);
    const int cb = bn + wn * 64 + 2 * (lane & 3);
#pragma unroll
    for (int m = 0; m < 4; ++m) {
#pragma unroll
        for (int n = 0; n < 8; ++n) {
            const int cc = cb + n * 8;
#pragma unroll
            for (int hf = 0; hf < 2; ++hf) {
                const int r = rb + m * 16 + hf * 8;
                if (r < Mreal) {
                    float2 o;
                    o.x = acc[m][n][2 * hf + 0];
                    o.y = acc[m][n][2 * hf + 1];
                    *(float2*)&C[(size_t)r * REP + cc] = o;
                }
            }
        }
    }
}

// reduce split-K partials + bias + relu -> gH1f
__global__ void reduce_bias_relu(const float* __restrict__ b1) {
    const int idx = blockIdx.x * 256 + threadIdx.x;   // per float4 over N_ROIS*REP
    if (idx >= N_ROIS * REP / 4) return;
    const size_t e = (size_t)idx * 4;
    const int col = (int)(e & (REP - 1));
    const float4 p0 = *(const float4*)(gPart + e);
    const float4 p1 = *(const float4*)(gPart + (size_t)MPAD * REP + e);
    const float4 bb = *(const float4*)(b1 + col);
    float4 o;
    o.x = fmaxf(p0.x + p1.x + bb.x, 0.f);
    o.y = fmaxf(p0.y + p1.y + bb.y, 0.f);
    o.z = fmaxf(p0.z + p1.z + bb.z, 0.f);
    o.w = fmaxf(p0.w + p1.w + bb.w, 0.f);
    *(float4*)(gH1f + e) = o;
}

// ======================= 256-thread fused-split GEMM (BN templated) =======================
template <int BN>
__global__ void __launch_bounds__(256, 1) hgemmF(
    const float* __restrict__ A, const float* __restrict__ B,
    const float* __restrict__ bias, int K, int lda, int ldb,
    int Mreal, int relu, float* __restrict__ C, int ldc)
{
    constexpr int ROWB  = BN * 2;
    constexpr int BTILE = 32 * ROWB;
    constexpr int STG   = 16384 + 2 * BTILE;
    constexpr int BJ    = (BN == 128) ? 4 : 2;
    constexpr int NWN   = BN / 32;
    constexpr int MF    = BN / 32;

    extern __shared__ __align__(16) char smem[];
    const uint32_t sb = s2u(smem);
    const int tid = threadIdx.x;
    const int lane = tid & 31, wid = tid >> 5;
    const int wn = wid % NWN, wm = wid / NWN;
    const int wmbase = wm * (MF * 16);
    const int bm = blockIdx.y * 128, bn = blockIdx.x * BN;
    const int niter = K >> 5;

    float acc[MF][4][4];
#pragma unroll
    for (int m = 0; m < MF; ++m)
#pragma unroll
        for (int n = 0; n < 4; ++n)
#pragma unroll
            for (int e = 0; e < 4; ++e) acc[m][n][e] = 0.f;

    float4 aS[4];
    float4 bS[BJ];
    const int r0 = tid >> 3, seg = tid & 7;

    auto ldgA = [&](int i) {
        const int k0 = i * 32;
#pragma unroll
        for (int j = 0; j < 4; ++j) {
            const int gr = bm + r0 + 32 * j;
            if (gr < Mreal) aS[j] = *(const float4*)(A + (size_t)gr * lda + k0 + seg * 4);
            else aS[j] = make_float4(0.f, 0.f, 0.f, 0.f);
        }
    };
    auto ldgB = [&](int i) {
        const int k0 = i * 32;
#pragma unroll
        for (int j = 0; j < BJ; ++j) {
            const int nf = seg * 4 + j * 32;
            bS[j] = *(const float4*)(B + (size_t)(k0 + r0) * ldb + bn + nf);
        }
    };
    auto stsStage = [&](int i) {
        char* st = smem + (size_t)(i % 3) * STG;
#pragma unroll
        for (int j = 0; j < 4; ++j) {
            const int row = r0 + 32 * j;
            __half h0, l0, h1, l1, h2, l2, h3, l3;
            split2u(aS[j].x, h0, l0); split2u(aS[j].y, h1, l1);
            split2u(aS[j].z, h2, l2); split2u(aS[j].w, h3, l3);
            uint32_t relh = (uint32_t)(row * 128 + seg * 8);
            relh ^= (relh >> 3) & 0x70;
            uint32_t rell = (uint32_t)(row * 128 + 64 + seg * 8);
            rell ^= (rell >> 3) & 0x70;
            uint2 vh; vh.x = pack2(h0, h1); vh.y = pack2(h2, h3);
            uint2 vl; vl.x = pack2(l0, l1); vl.y = pack2(l2, l3);
            *(uint2*)(st + relh) = vh;
            *(uint2*)(st + rell) = vl;
        }
#pragma unroll
        for (int j = 0; j < BJ; ++j) {
            const int nf = seg * 4 + j * 32;
            __half h0, l0, h1, l1, h2, l2, h3, l3;
            split2u(bS[j].x, h0, l0); split2u(bS[j].y, h1, l1);
            split2u(bS[j].z, h2, l2); split2u(bS[j].w, h3, l3);
            uint32_t rel = (uint32_t)(r0 * ROWB + nf * 2);
            if (BN == 128) rel ^= ((rel >> 8) & 7) << 4;
            else           rel ^= ((rel >> 7) & 7) << 4;
            uint2 vh; vh.x = pack2(h0, h1); vh.y = pack2(h2, h3);
            uint2 vl; vl.x = pack2(l0, l1); vl.y = pack2(l2, l3);
            *(uint2*)(st + 16384 + rel) = vh;
            *(uint2*)(st + 16384 + BTILE + rel) = vl;
        }
    };
    auto compute = [&](int i) {
        const uint32_t ab = sb + (uint32_t)(i % 3) * STG;
        const uint32_t bb = ab + 16384;
#pragma unroll
        for (int kk = 0; kk < 2; ++kk) {
            uint32_t Af[MF][4], Lf[MF][4], Bf[4][2], Mf[4][2];
#pragma unroll
            for (int m = 0; m < MF; ++m) {
                const int row = wmbase + m * 16 + (lane & 15);
                const int colb = kk * 32 + ((lane >> 4) << 4);
                uint32_t rr1 = (uint32_t)(row * 128 + colb);
                uint32_t rr2 = (uint32_t)(row * 128 + 64 + colb);
                rr1 ^= (rr1 >> 3) & 0x70;
                rr2 ^= (rr2 >> 3) & 0x70;
                ldm4(Af[m], ab + rr1);
                ldm4(Lf[m], ab + rr2);
            }
#pragma unroll
            for (int p = 0; p < 2; ++p) {
                const int grp = lane >> 3, kr = lane & 7;
                const int kx = kk * 16 + (grp & 1) * 8 + kr;
                const int nb = wn * 32 + p * 16 + (grp >> 1) * 8;
                uint32_t rel = (uint32_t)(kx * ROWB + nb * 2);
                if (BN == 128) rel ^= ((rel >> 8) & 7) << 4;
                else           rel ^= ((rel >> 7) & 7) << 4;
                uint32_t t[4];
                ldm4t(t, bb + rel);
                Bf[2 * p][0] = t[0]; Bf[2 * p][1] = t[1];
                Bf[2 * p + 1][0] = t[2]; Bf[2 * p + 1][1] = t[3];
                ldm4t(t, bb + BTILE + rel);
                Mf[2 * p][0] = t[0]; Mf[2 * p][1] = t[1];
                Mf[2 * p + 1][0] = t[2]; Mf[2 * p + 1][1] = t[3];
            }
#pragma unroll
            for (int m = 0; m < MF; ++m)
#pragma unroll
                for (int n = 0; n < 4; ++n) {
                    mma_f16(acc[m][n], Af[m], Bf[n]);
                    mma_f16(acc[m][n], Af[m], Mf[n]);
                    mma_f16(acc[m][n], Lf[m], Bf[n]);
                }
        }
    };

    ldgA(0); ldgB(0);
    stsStage(0);
    if (niter > 1) { ldgA(1); ldgB(1); }
    __syncthreads();
    for (int i = 0; i < niter; ++i) {
        if (i + 1 < niter) stsStage(i + 1);
        if (i + 2 < niter) { ldgA(i + 2); ldgB(i + 2); }
        __syncthreads();
        compute(i);
    }

    const int rb = bm + wmbase + (lane >> 2);
    const int cb = bn + wn * 32 + 2 * (lane & 3);
#pragma unroll
    for (int m = 0; m < MF; ++m) {
#pragma unroll
        for (int n = 0; n < 4; ++n) {
            const int cc = cb + n * 8;
            const float2 bi = *(const float2*)&bias[cc];
#pragma unroll
            for (int hf = 0; hf < 2; ++hf) {
                const int r = rb + m * 16 + hf * 8;
                if (r < Mreal) {
                    float v0 = acc[m][n][2 * hf + 0] + bi.x;
                    float v1 = acc[m][n][2 * hf + 1] + bi.y;
                    if (relu) { v0 = fmaxf(v0, 0.f); v1 = fmaxf(v1, 0.f); }
                    float2 o; o.x = v0; o.y = v1;
                    *(float2*)&C[(size_t)r * ldc + cc] = o;
                }
            }
        }
    }
}

// ======================= softmax =======================
__global__ void softmax_kernel() {
    const int n = blockIdx.x;
    const int lane = threadIdx.x;
    float v[3];
    float mx = -3.4e38f;
#pragma unroll
    for (int t = 0; t < 3; ++t) {
        const int i = lane + 32 * t;
        v[t] = (i < NCLS) ? g_comb[(size_t)n * NHEAD + i] : -3.4e38f;
        mx = fmaxf(mx, v[t]);
    }
#pragma unroll
    for (int s = 16; s > 0; s >>= 1) mx = fmaxf(mx, __shfl_xor_sync(0xffffffffu, mx, s));
    float sum = 0.f;
#pragma unroll
    for (int t = 0; t < 3; ++t) {
        const int i = lane + 32 * t;
        if (i < NCLS) { v[t] = expf(v[t] - mx); sum += v[t]; }
    }
#pragma unroll
    for (int s = 16; s > 0; s >>= 1) sum += __shfl_xor_sync(0xffffffffu, sum, s);
#pragma unroll
    for (int t = 0; t < 3; ++t) {
        const int i = lane + 32 * t;
        if (i < NCLS) g_scores[n * NCLS + i] = v[t] / sum;
    }
}

// ======================= per-class NMS =======================
#define CSMEM (4 * NPAD * 4 + NPAD * 8 + NPAD)

__global__ void __launch_bounds__(256) class_nms(
    const float* __restrict__ P, const int* __restrict__ imh, const int* __restrict__ imw)
{
    extern __shared__ __align__(16) char smemraw[];
    float* sx1 = (float*)smemraw;
    float* sy1 = sx1 + NPAD;
    float* sx2 = sy1 + NPAD;
    float* sy2 = sx2 + NPAD;
    unsigned long long* keys = (unsigned long long*)(sy2 + NPAD);
    char* alive = (char*)(keys + NPAD);
    __shared__ int s_nsurv;

    const int tid = threadIdx.x;
    const int cls = blockIdx.x;
    const int c = cls + 1;
    const float Wim = (float)(*imw);
    const float Him = (float)(*imh);
    const float offv = (float)c * (fmaxf(Wim, Him) + 1.0f);

    if (tid == 0) s_nsurv = 0;

    for (int n = tid; n < NPAD; n += 256) {
        unsigned long long key = 0ull;
        if (n < N_ROIS) {
            float x1, y1, x2, y2;
            decode_one(n, c, P, Wim, Him, x1, y1, x2, y2);
            const float s = g_scores[n * NCLS + c];
            if (s > 0.05f && (x2 - x1) >= 0.01f && (y2 - y1) >= 0.01f) {
                sx1[n] = x1 + offv;
                sy1[n] = y1 + offv;
                sx2[n] = x2 + offv;
                sy2[n] = y2 + offv;
                key = ((unsigned long long)__float_as_uint(s) << 32)
                    | (unsigned long long)(0xFFFFFFFFu - (unsigned)n);
            }
        }
        keys[n] = key;
        alive[n] = 1;
    }
    __syncthreads();

    for (int k = 2; k <= NPAD; k <<= 1) {
        for (int j = k >> 1; j > 0; j >>= 1) {
            for (int i = tid; i < NPAD; i += 256) {
                const int l = i ^ j;
                if (l > i) {
                    const unsigned long long a = keys[i], b = keys[l];
                    const bool up = ((i & k) == 0);
                    if (up ? (a < b) : (a > b)) { keys[i] = b; keys[l] = a; }
                }
            }
            __syncthreads();
        }
    }

    for (int pos = 0; pos < NPAD; ++pos) {
        const unsigned long long k = keys[pos];
        if (k == 0ull) break;
        if (!alive[pos]) continue;
        if (s_nsurv >= MAXDET) break;
        const int ni = (int)(0xFFFFFFFFu - (unsigned)(k & 0xFFFFFFFFull));
        const float bx1 = sx1[ni], by1 = sy1[ni], bx2 = sx2[ni], by2 = sy2[ni];
        const float ai = (bx2 - bx1) * (by2 - by1);
        if (tid == 0) {
            const unsigned flat = (unsigned)(ni * NC1 + cls);
            g_surv[cls * MAXDET + s_nsurv] =
                (k & 0xFFFFFFFF00000000ull) | (unsigned long long)(0xFFFFFFFFu - flat);
            s_nsurv++;
        }
        for (int j = pos + 1 + tid; j < NPAD; j += 256) {
            if (!alive[j]) continue;
            const unsigned long long k2 = keys[j];
            if (k2 == 0ull) continue;
            const int nj = (int)(0xFFFFFFFFu - (unsigned)(k2 & 0xFFFFFFFFull));
            const float xx1 = fmaxf(bx1, sx1[nj]);
            const float yy1 = fmaxf(by1, sy1[nj]);
            const float xx2 = fminf(bx2, sx2[nj]);
            const float yy2 = fminf(by2, sy2[nj]);
            const float inter = fmaxf(xx2 - xx1, 0.f) * fmaxf(yy2 - yy1, 0.f);
            const float aj = (sx2[nj] - sx1[nj]) * (sy2[nj] - sy1[nj]);
            const float iou = inter / (ai + aj - inter + 1e-9f);
            if (iou > 0.5f) alive[j] = 0;
        }
        __syncthreads();
    }
    __syncthreads();
    if (tid == 0) g_snum[cls] = s_nsurv;
}

// ======================= merge + output =======================
__global__ void __launch_bounds__(128) final_select(
    const float* __restrict__ P, const int* __restrict__ imh, const int* __restrict__ imw,
    float* __restrict__ out, int out_size)
{
    __shared__ unsigned long long red[128];
    __shared__ int heads[NC1];
    __shared__ int cnts[NC1];
    __shared__ int keep[MAXDET];
    __shared__ int s_w;

    const int tid = threadIdx.x;
    if (tid < NC1) { heads[tid] = 0; cnts[tid] = g_snum[tid]; }
    if (tid < MAXDET) keep[tid] = -1;
    __syncthreads();

    for (int it = 0; it < MAXDET; ++it) {
        unsigned long long cand = 0ull;
        if (tid < NC1 && heads[tid] < cnts[tid])
            cand = g_surv[tid * MAXDET + heads[tid]];
        red[tid] = cand;
        __syncthreads();
        for (int s = 64; s > 0; s >>= 1) {
            if (tid < s) { if (red[tid + s] > red[tid]) red[tid] = red[tid + s]; }
            __syncthreads();
        }
        const unsigned long long best = red[0];
        if (best == 0ull) break;
        if (tid < NC1 && cand == best) s_w = tid;
        __syncthreads();
        if (tid == 0) {
            heads[s_w]++;
            keep[it] = (int)(0xFFFFFFFFu - (unsigned)(best & 0xFFFFFFFFull));
        }
        __syncthreads();
    }

    if (tid < MAXDET) {
        const int k = keep[tid];
        float b0 = 0, b1 = 0, b2 = 0, b3 = 0, s = 0, l = 0;
        if (k >= 0) {
            const int n = k / NC1;
            const int c = k % NC1 + 1;
            const float Wim = (float)(*imw);
            const float Him = (float)(*imh);
            float x1, y1, x2, y2;
            decode_one(n, c, P, Wim, Him, x1, y1, x2, y2);
            b0 = x1; b1 = y1; b2 = x2; b3 = y2;
            s = g_scores[n * NCLS + c];
            l = (float)c;
        }
        if (tid * 4 + 3 < out_size) {
            out[tid * 4 + 0] = b0;
            out[tid * 4 + 1] = b1;
            out[tid * 4 + 2] = b2;
            out[tid * 4 + 3] = b3;
        }
        if (4 * MAXDET + tid < out_size) out[4 * MAXDET + tid] = s;
        if (5 * MAXDET + tid < out_size) out[5 * MAXDET + tid] = l;
    }
}

// ======================= launch =======================
extern "C" void kernel_launch(void* const* d_in, const int* in_sizes, int n_in,
                              void* d_out, int out_size) {
    const float* X  = (const float*)d_in[0];
    const float* P  = (const float*)d_in[1];
    const float* W1 = (const float*)d_in[2];
    const float* b1 = (const float*)d_in[3];
    const float* W2 = (const float*)d_in[4];
    const float* b2 = (const float*)d_in[5];
    const float* Wc = (const float*)d_in[6];
    const float* bc = (const float*)d_in[7];
    const float* Wr = (const float*)d_in[8];
    const float* br = (const float*)d_in[9];
    const int* imh  = (const int*)d_in[10];
    const int* imw  = (const int*)d_in[11];

    float *pWh, *pBiasH, *pPart, *pH1, *pH2, *pComb;
    cudaGetSymbolAddress((void**)&pWh, gWhf);
    cudaGetSymbolAddress((void**)&pBiasH, gBiasH);
    cudaGetSymbolAddress((void**)&pPart, gPart);
    cudaGetSymbolAddress((void**)&pH1, gH1f);
    cudaGetSymbolAddress((void**)&pH2, gH2f);
    cudaGetSymbolAddress((void**)&pComb, g_comb);

    const int SMEM128 = 3 * (16384 + 2 * (32 * 256));   // 98304
    const int SMEM64  = 3 * (16384 + 2 * (32 * 128));   // 73728
    cudaFuncSetAttribute(hgemmW, cudaFuncAttributeMaxDynamicSharedMemorySize, SMEMW);
    cudaFuncSetAttribute(hgemmF<128>, cudaFuncAttributeMaxDynamicSharedMemorySize, SMEM128);
    cudaFuncSetAttribute(hgemmF<64>,  cudaFuncAttributeMaxDynamicSharedMemorySize, SMEM64);
    cudaFuncSetAttribute(class_nms, cudaFuncAttributeMaxDynamicSharedMemorySize, CSMEM);

    build_headW<<<REP * NHEAD / 256, 256>>>(Wc, Wr);
    build_bias<<<(NHEAD + 255) / 256, 256>>>(bc, br);

    // GEMM1 (split-K=2): parts = X @ W1; then h1 = relu(sum + b1)
    hgemmW<<<dim3(REP / 256, MPAD / 128, 2), 256, SMEMW>>>(
        X, W1, IN_F, REP, N_ROIS, IN_F / 2, pPart);
    reduce_bias_relu<<<(N_ROIS * REP / 4 + 255) / 256, 256>>>(b1);

    // GEMM2: h2 = relu(h1 @ W2 + b2)
    hgemmF<128><<<dim3(REP / 128, MPAD / 128), 256, SMEM128>>>(
        pH1, W2, b2, REP, REP, REP, N_ROIS, 1, pH2, REP);
    // heads: comb = h2 @ Wh + biasH
    hgemmF<64><<<dim3(NHEAD / 64, MPAD / 128), 256, SMEM64>>>(
        pH2, pWh, pBiasH, REP, REP, NHEAD, N_ROIS, 0, pComb, NHEAD);

    softmax_kernel<<<N_ROIS, 32>>>();
    class_nms<<<NC1, 256, CSMEM>>>(P, imh, imw);
    final_select<<<1, 128>>>(P, imh, imw, (float*)d_out, out_size);
}

// round 14
// speedup vs baseline: 1.0585x; 1.0585x over previous
#include <cuda_runtime.h>
#include <cuda_fp16.h>
#include <math.h>
#include <stdint.h>

#define N_ROIS 2000
#define MPAD   2048
#define IN_F   12544
#define REP    1024
#define NHEAD  512
#define NCLS   91
#define NC1    90
#define NPAD   2048
#define BBOX_CLIP_F 4.135166556742356f
#define MAXDET 100

// ======================= static scratch (no allocs; zero-initialized) =======================
__device__ __half gA_hi[MPAD * IN_F];
__device__ __half gA_lo[MPAD * IN_F];
__device__ __half gW1_hi[REP * IN_F];
__device__ __half gW1_lo[REP * IN_F];
__device__ __half gW2_hi[REP * REP];
__device__ __half gW2_lo[REP * REP];
__device__ __half gWh_hi[NHEAD * REP];
__device__ __half gWh_lo[NHEAD * REP];
__device__ __half gH1_hi[MPAD * REP];
__device__ __half gH1_lo[MPAD * REP];
__device__ __half gH2_hi[MPAD * REP];
__device__ __half gH2_lo[MPAD * REP];
__device__ float gBiasH[NHEAD];
__device__ float g_comb[N_ROIS * NHEAD];     // logits cols 0..90, breg cols 92+4c
__device__ float g_scores[N_ROIS * NCLS];
__device__ unsigned long long g_surv[NC1 * MAXDET];
__device__ int g_snum[NC1];

// ======================= helpers =======================
__device__ __forceinline__ uint32_t s2u(const void* p) {
    uint32_t a;
    asm("{ .reg .u64 t; cvta.to.shared.u64 t, %1; cvt.u32.u64 %0, t; }" : "=r"(a) : "l"(p));
    return a;
}
__device__ __forceinline__ void ldm4(uint32_t* r, uint32_t addr) {
    asm volatile("ldmatrix.sync.aligned.m8n8.x4.shared.b16 {%0,%1,%2,%3}, [%4];"
                 : "=r"(r[0]), "=r"(r[1]), "=r"(r[2]), "=r"(r[3]) : "r"(addr));
}
__device__ __forceinline__ void mma_f16(float* d, const uint32_t* a, const uint32_t* b) {
    asm volatile(
        "mma.sync.aligned.m16n8k16.row.col.f32.f16.f16.f32 "
        "{%0,%1,%2,%3}, {%4,%5,%6,%7}, {%8,%9}, {%0,%1,%2,%3};"
        : "+f"(d[0]), "+f"(d[1]), "+f"(d[2]), "+f"(d[3])
        : "r"(a[0]), "r"(a[1]), "r"(a[2]), "r"(a[3]), "r"(b[0]), "r"(b[1]));
}
// unscaled split: x = h + l (residual ~2^-25 abs loss, negligible)
__device__ __forceinline__ void split2u(float x, __half& h, __half& l) {
    h = __float2half_rn(x);
    l = __float2half_rn(x - __half2float(h));
}
__device__ __forceinline__ void decode_one(
    int n, int c, const float* __restrict__ P, float Wim, float Him,
    float& x1, float& y1, float& x2, float& y2)
{
    const float4 p = *reinterpret_cast<const float4*>(&P[n * 4]);
    const float pw = p.z - p.x;
    const float ph = p.w - p.y;
    const float pcx = p.x + 0.5f * pw;
    const float pcy = p.y + 0.5f * ph;
    const float4 r = *reinterpret_cast<const float4*>(&g_comb[(size_t)n * NHEAD + 92 + c * 4]);
    const float dx = r.x / 10.0f;
    const float dy = r.y / 10.0f;
    const float dw = fminf(r.z / 5.0f, BBOX_CLIP_F);
    const float dh = fminf(r.w / 5.0f, BBOX_CLIP_F);
    const float cx = dx * pw + pcx;
    const float cy = dy * ph + pcy;
    const float w = expf(dw) * pw;
    const float hh = expf(dh) * ph;
    x1 = fminf(fmaxf(cx - 0.5f * w, 0.f), Wim);
    y1 = fminf(fmaxf(cy - 0.5f * hh, 0.f), Him);
    x2 = fminf(fmaxf(cx + 0.5f * w, 0.f), Wim);
    y2 = fminf(fmaxf(cy + 0.5f * hh, 0.f), Him);
}

// ======================= pre-pass kernels =======================
__global__ void split_X(const float* __restrict__ X) {
    const int idx = blockIdx.x * 256 + threadIdx.x;   // one float4
    if (idx >= N_ROIS * IN_F / 4) return;
    const size_t e = (size_t)idx * 4;
    const float4 v = *(const float4*)(X + e);
    __half h0, l0, h1, l1, h2, l2, h3, l3;
    split2u(v.x, h0, l0); split2u(v.y, h1, l1);
    split2u(v.z, h2, l2); split2u(v.w, h3, l3);
    __half2 t;
    t.x = h0; t.y = h1; *(__half2*)(gA_hi + e) = t;
    t.x = h2; t.y = h3; *(__half2*)(gA_hi + e + 2) = t;
    t.x = l0; t.y = l1; *(__half2*)(gA_lo + e) = t;
    t.x = l2; t.y = l3; *(__half2*)(gA_lo + e + 2) = t;
}

// transpose + split: W [K x N] fp32 -> out [N x K] fp16 x2
__global__ void tsplitW(const float* __restrict__ W,
                        __half* __restrict__ Oh, __half* __restrict__ Ol, int K, int N) {
    __shared__ float t[32][33];
    const int k0 = blockIdx.x * 32, n0 = blockIdx.y * 32;
    const int tx = threadIdx.x, ty = threadIdx.y;
#pragma unroll
    for (int i = 0; i < 4; ++i)
        t[ty + 8 * i][tx] = W[(size_t)(k0 + ty + 8 * i) * N + n0 + tx];
    __syncthreads();
#pragma unroll
    for (int i = 0; i < 4; ++i) {
        const float v = t[tx][ty + 8 * i];
        __half h, l;
        split2u(v, h, l);
        const size_t o = (size_t)(n0 + ty + 8 * i) * K + k0 + tx;
        Oh[o] = h; Ol[o] = l;
    }
}

__global__ void build_head(const float* __restrict__ Wc, const float* __restrict__ Wr) {
    const int n = blockIdx.x;
    const int k = blockIdx.y * 256 + threadIdx.x;
    float v = 0.f;
    if (n < NCLS) v = Wc[(size_t)k * NCLS + n];
    else if (n >= 92 && n < 92 + 4 * NCLS) v = Wr[(size_t)k * (4 * NCLS) + (n - 92)];
    __half h, l;
    split2u(v, h, l);
    const size_t o = (size_t)n * REP + k;
    gWh_hi[o] = h; gWh_lo[o] = l;
}

__global__ void build_bias(const float* __restrict__ bc, const float* __restrict__ br) {
    const int c = blockIdx.x * 256 + threadIdx.x;
    if (c >= NHEAD) return;
    float v = 0.f;
    if (c < NCLS) v = bc[c];
    else if (c >= 92 && c < 92 + 4 * NCLS) v = br[c - 92];
    gBiasH[c] = v;
}

// ======================= HMMA GEMM: cp.async loader, single fp32 acc, 2 CTAs/SM =======================
// C = A[M,K] @ B[N,K]^T. acc += Ah*Bh + Ah*Bl + Al*Bh (lo unscaled).
// 8 warps, warp tile 64x32. 3-stage cp.async pipeline, 96KB smem -> 2 CTAs/SM.
#define STAGE_B 32768
#define NSTAGE 3
#define SMEM_GEMM (NSTAGE * STAGE_B)

__global__ void __launch_bounds__(256, 2) hgemm(
    const __half* __restrict__ Ah, const __half* __restrict__ Al,
    const __half* __restrict__ Bh, const __half* __restrict__ Bl,
    const float* __restrict__ bias, int K, int Mreal, int mode,
    float* __restrict__ C, int ldc,
    __half* __restrict__ Oh, __half* __restrict__ Ol, int ldo)
{
    extern __shared__ __align__(16) char smem[];
    const uint32_t sb = s2u(smem);
    const int tid = threadIdx.x;
    const int lane = tid & 31, wid = tid >> 5;
    const int wm = wid & 1, wn = wid >> 1;           // warp tile: 64x32 at (wm*64, wn*32)
    const int bm = blockIdx.y * 128, bn = blockIdx.x * 128;
    const int niter = K >> 5;

    float acc[4][4][4];
#pragma unroll
    for (int m = 0; m < 4; ++m)
#pragma unroll
        for (int n = 0; n < 4; ++n)
#pragma unroll
            for (int e = 0; e < 4; ++e) acc[m][n][e] = 0.f;

    auto load_stage = [&](int st, int k0) {
#pragma unroll
        for (int j = 0; j < 8; ++j) {
            const int q = j * 256 + tid;
            const int isB = q >> 10;
            const int sp = (q >> 9) & 1;
            const int row = (q >> 2) & 127;
            const int seg = q & 3;
            uint32_t rel = (uint32_t)(row * 128 + sp * 64 + seg * 16);
            rel ^= (rel >> 3) & 0x70;
            const uint32_t dst = sb + (uint32_t)st * STAGE_B + (uint32_t)isB * 16384 + rel;
            const __half* src;
            if (isB) src = (sp ? Bl : Bh) + (size_t)(bn + row) * K + k0 + seg * 8;
            else     src = (sp ? Al : Ah) + (size_t)(bm + row) * K + k0 + seg * 8;
            asm volatile("cp.async.cg.shared.global [%0], [%1], 16;" :: "r"(dst), "l"(src));
        }
    };

    auto compute_stage = [&](int st) {
        const uint32_t ab = sb + (uint32_t)st * STAGE_B;
        const uint32_t bb = ab + 16384;
#pragma unroll
        for (int kk = 0; kk < 2; ++kk) {
            uint32_t Af[4][4], Lf[4][4], Bf[4][2], Mf[4][2];
#pragma unroll
            for (int m = 0; m < 4; ++m) {
                const int row = wm * 64 + m * 16 + (lane & 15);
                const int colb = kk * 32 + ((lane >> 4) << 4);
                uint32_t r1 = (uint32_t)(row * 128 + colb);
                uint32_t r2 = (uint32_t)(row * 128 + 64 + colb);
                r1 ^= (r1 >> 3) & 0x70;
                r2 ^= (r2 >> 3) & 0x70;
                ldm4(Af[m], ab + r1);
                ldm4(Lf[m], ab + r2);
            }
#pragma unroll
            for (int p = 0; p < 2; ++p) {
                const int mm = lane >> 3;
                const int row = wn * 32 + p * 16 + ((mm >> 1) << 3) + (lane & 7);
                const int colb = kk * 32 + ((mm & 1) << 4);
                uint32_t r1 = (uint32_t)(row * 128 + colb);
                uint32_t r2 = (uint32_t)(row * 128 + 64 + colb);
                r1 ^= (r1 >> 3) & 0x70;
                r2 ^= (r2 >> 3) & 0x70;
                uint32_t t[4];
                ldm4(t, bb + r1);
                Bf[2 * p][0] = t[0]; Bf[2 * p][1] = t[1];
                Bf[2 * p + 1][0] = t[2]; Bf[2 * p + 1][1] = t[3];
                ldm4(t, bb + r2);
                Mf[2 * p][0] = t[0]; Mf[2 * p][1] = t[1];
                Mf[2 * p + 1][0] = t[2]; Mf[2 * p + 1][1] = t[3];
            }
#pragma unroll
            for (int m = 0; m < 4; ++m)
#pragma unroll
                for (int n = 0; n < 4; ++n) {
                    mma_f16(acc[m][n], Af[m], Bf[n]);
                    mma_f16(acc[m][n], Af[m], Mf[n]);
                    mma_f16(acc[m][n], Lf[m], Bf[n]);
                }
        }
    };

    // 3-stage pipeline: 2 loads in flight
    for (int p = 0; p < 2; ++p) {
        if (p < niter) load_stage(p, p * 32);
        asm volatile("cp.async.commit_group;" ::: "memory");
    }
    for (int i = 0; i < niter; ++i) {
        asm volatile("cp.async.wait_group 1;" ::: "memory");
        __syncthreads();
        const int nxt = i + 2;
        if (nxt < niter) load_stage(nxt % NSTAGE, nxt * 32);
        asm volatile("cp.async.commit_group;" ::: "memory");
        compute_stage(i % NSTAGE);
    }
    asm volatile("cp.async.wait_group 0;" ::: "memory");

    // epilogue
    const int rb = bm + wm * 64 + (lane >> 2);
    const int cb = bn + wn * 32 + 2 * (lane & 3);
#pragma unroll
    for (int m = 0; m < 4; ++m) {
#pragma unroll
        for (int n = 0; n < 4; ++n) {
            const int cc = cb + n * 8;
            const float2 bi = *(const float2*)&bias[cc];
#pragma unroll
            for (int hf = 0; hf < 2; ++hf) {
                const int r = rb + m * 16 + hf * 8;
                if (r < Mreal) {
                    float v0 = acc[m][n][2 * hf + 0] + bi.x;
                    float v1 = acc[m][n][2 * hf + 1] + bi.y;
                    if (mode == 0) {
                        float2 o; o.x = v0; o.y = v1;
                        *(float2*)&C[(size_t)r * ldc + cc] = o;
                    } else {
                        v0 = fmaxf(v0, 0.f);
                        v1 = fmaxf(v1, 0.f);
                        __half h0, l0, h1, l1;
                        split2u(v0, h0, l0);
                        split2u(v1, h1, l1);
                        __half2 th; th.x = h0; th.y = h1;
                        __half2 tl; tl.x = l0; tl.y = l1;
                        *(__half2*)&Oh[(size_t)r * ldo + cc] = th;
                        *(__half2*)&Ol[(size_t)r * ldo + cc] = tl;
                    }
                }
            }
        }
    }
}

// ======================= softmax =======================
__global__ void softmax_kernel() {
    const int n = blockIdx.x;
    const int lane = threadIdx.x;
    float v[3];
    float mx = -3.4e38f;
#pragma unroll
    for (int t = 0; t < 3; ++t) {
        const int i = lane + 32 * t;
        v[t] = (i < NCLS) ? g_comb[(size_t)n * NHEAD + i] : -3.4e38f;
        mx = fmaxf(mx, v[t]);
    }
#pragma unroll
    for (int s = 16; s > 0; s >>= 1) mx = fmaxf(mx, __shfl_xor_sync(0xffffffffu, mx, s));
    float sum = 0.f;
#pragma unroll
    for (int t = 0; t < 3; ++t) {
        const int i = lane + 32 * t;
        if (i < NCLS) { v[t] = expf(v[t] - mx); sum += v[t]; }
    }
#pragma unroll
    for (int s = 16; s > 0; s >>= 1) sum += __shfl_xor_sync(0xffffffffu, sum, s);
#pragma unroll
    for (int t = 0; t < 3; ++t) {
        const int i = lane + 32 * t;
        if (i < NCLS) g_scores[n * NCLS + i] = v[t] / sum;
    }
}

// ======================= per-class NMS =======================
#define CSMEM (4 * NPAD * 4 + NPAD * 8 + NPAD)

__global__ void __launch_bounds__(256) class_nms(
    const float* __restrict__ P, const int* __restrict__ imh, const int* __restrict__ imw)
{
    extern __shared__ __align__(16) char smemraw[];
    float* sx1 = (float*)smemraw;
    float* sy1 = sx1 + NPAD;
    float* sx2 = sy1 + NPAD;
    float* sy2 = sx2 + NPAD;
    unsigned long long* keys = (unsigned long long*)(sy2 + NPAD);
    char* alive = (char*)(keys + NPAD);
    __shared__ int s_nsurv;

    const int tid = threadIdx.x;
    const int cls = blockIdx.x;
    const int c = cls + 1;
    const float Wim = (float)(*imw);
    const float Him = (float)(*imh);
    const float offv = (float)c * (fmaxf(Wim, Him) + 1.0f);

    if (tid == 0) s_nsurv = 0;

    for (int n = tid; n < NPAD; n += 256) {
        unsigned long long key = 0ull;
        if (n < N_ROIS) {
            float x1, y1, x2, y2;
            decode_one(n, c, P, Wim, Him, x1, y1, x2, y2);
            const float s = g_scores[n * NCLS + c];
            if (s > 0.05f && (x2 - x1) >= 0.01f && (y2 - y1) >= 0.01f) {
                sx1[n] = x1 + offv;
                sy1[n] = y1 + offv;
                sx2[n] = x2 + offv;
                sy2[n] = y2 + offv;
                key = ((unsigned long long)__float_as_uint(s) << 32)
                    | (unsigned long long)(0xFFFFFFFFu - (unsigned)n);
            }
        }
        keys[n] = key;
        alive[n] = 1;
    }
    __syncthreads();

    for (int k = 2; k <= NPAD; k <<= 1) {
        for (int j = k >> 1; j > 0; j >>= 1) {
            for (int i = tid; i < NPAD; i += 256) {
                const int l = i ^ j;
                if (l > i) {
                    const unsigned long long a = keys[i], b = keys[l];
                    const bool up = ((i & k) == 0);
                    if (up ? (a < b) : (a > b)) { keys[i] = b; keys[l] = a; }
                }
            }
            __syncthreads();
        }
    }

    for (int pos = 0; pos < NPAD; ++pos) {
        const unsigned long long k = keys[pos];
        if (k == 0ull) break;
        if (!alive[pos]) continue;
        if (s_nsurv >= MAXDET) break;
        const int ni = (int)(0xFFFFFFFFu - (unsigned)(k & 0xFFFFFFFFull));
        const float bx1 = sx1[ni], by1 = sy1[ni], bx2 = sx2[ni], by2 = sy2[ni];
        const float ai = (bx2 - bx1) * (by2 - by1);
        if (tid == 0) {
            const unsigned flat = (unsigned)(ni * NC1 + cls);
            g_surv[cls * MAXDET + s_nsurv] =
                (k & 0xFFFFFFFF00000000ull) | (unsigned long long)(0xFFFFFFFFu - flat);
            s_nsurv++;
        }
        for (int j = pos + 1 + tid; j < NPAD; j += 256) {
            if (!alive[j]) continue;
            const unsigned long long k2 = keys[j];
            if (k2 == 0ull) continue;
            const int nj = (int)(0xFFFFFFFFu - (unsigned)(k2 & 0xFFFFFFFFull));
            const float xx1 = fmaxf(bx1, sx1[nj]);
            const float yy1 = fmaxf(by1, sy1[nj]);
            const float xx2 = fminf(bx2, sx2[nj]);
            const float yy2 = fminf(by2, sy2[nj]);
            const float inter = fmaxf(xx2 - xx1, 0.f) * fmaxf(yy2 - yy1, 0.f);
            const float aj = (sx2[nj] - sx1[nj]) * (sy2[nj] - sy1[nj]);
            const float iou = inter / (ai + aj - inter + 1e-9f);
            if (iou > 0.5f) alive[j] = 0;
        }
        __syncthreads();
    }
    __syncthreads();
    if (tid == 0) g_snum[cls] = s_nsurv;
}

// ======================= merge + output =======================
__global__ void __launch_bounds__(128) final_select(
    const float* __restrict__ P, const int* __restrict__ imh, const int* __restrict__ imw,
    float* __restrict__ out, int out_size)
{
    __shared__ unsigned long long red[128];
    __shared__ int heads[NC1];
    __shared__ int cnts[NC1];
    __shared__ int keep[MAXDET];
    __shared__ int s_w;

    const int tid = threadIdx.x;
    if (tid < NC1) { heads[tid] = 0; cnts[tid] = g_snum[tid]; }
    if (tid < MAXDET) keep[tid] = -1;
    __syncthreads();

    for (int it = 0; it < MAXDET; ++it) {
        unsigned long long cand = 0ull;
        if (tid < NC1 && heads[tid] < cnts[tid])
            cand = g_surv[tid * MAXDET + heads[tid]];
        red[tid] = cand;
        __syncthreads();
        for (int s = 64; s > 0; s >>= 1) {
            if (tid < s) { if (red[tid + s] > red[tid]) red[tid] = red[tid + s]; }
            __syncthreads();
        }
        const unsigned long long best = red[0];
        if (best == 0ull) break;
        if (tid < NC1 && cand == best) s_w = tid;
        __syncthreads();
        if (tid == 0) {
            heads[s_w]++;
            keep[it] = (int)(0xFFFFFFFFu - (unsigned)(best & 0xFFFFFFFFull));
        }
        __syncthreads();
    }

    if (tid < MAXDET) {
        const int k = keep[tid];
        float b0 = 0, b1 = 0, b2 = 0, b3 = 0, s = 0, l = 0;
        if (k >= 0) {
            const int n = k / NC1;
            const int c = k % NC1 + 1;
            const float Wim = (float)(*imw);
            const float Him = (float)(*imh);
            float x1, y1, x2, y2;
            decode_one(n, c, P, Wim, Him, x1, y1, x2, y2);
            b0 = x1; b1 = y1; b2 = x2; b3 = y2;
            s = g_scores[n * NCLS + c];
            l = (float)c;
        }
        if (tid * 4 + 3 < out_size) {
            out[tid * 4 + 0] = b0;
            out[tid * 4 + 1] = b1;
            out[tid * 4 + 2] = b2;
            out[tid * 4 + 3] = b3;
        }
        if (4 * MAXDET + tid < out_size) out[4 * MAXDET + tid] = s;
        if (5 * MAXDET + tid < out_size) out[5 * MAXDET + tid] = l;
    }
}

// ======================= launch =======================
extern "C" void kernel_launch(void* const* d_in, const int* in_sizes, int n_in,
                              void* d_out, int out_size) {
    const float* X  = (const float*)d_in[0];
    const float* P  = (const float*)d_in[1];
    const float* W1 = (const float*)d_in[2];
    const float* b1 = (const float*)d_in[3];
    const float* W2 = (const float*)d_in[4];
    const float* b2 = (const float*)d_in[5];
    const float* Wc = (const float*)d_in[6];
    const float* bc = (const float*)d_in[7];
    const float* Wr = (const float*)d_in[8];
    const float* br = (const float*)d_in[9];
    const int* imh  = (const int*)d_in[10];
    const int* imw  = (const int*)d_in[11];

    __half *pAh, *pAl, *pW1h, *pW1l, *pW2h, *pW2l, *pWhh, *pWhl;
    __half *pH1h, *pH1l, *pH2h, *pH2l;
    float *pBiasH, *pComb;
    cudaGetSymbolAddress((void**)&pAh, gA_hi);
    cudaGetSymbolAddress((void**)&pAl, gA_lo);
    cudaGetSymbolAddress((void**)&pW1h, gW1_hi);
    cudaGetSymbolAddress((void**)&pW1l, gW1_lo);
    cudaGetSymbolAddress((void**)&pW2h, gW2_hi);
    cudaGetSymbolAddress((void**)&pW2l, gW2_lo);
    cudaGetSymbolAddress((void**)&pWhh, gWh_hi);
    cudaGetSymbolAddress((void**)&pWhl, gWh_lo);
    cudaGetSymbolAddress((void**)&pH1h, gH1_hi);
    cudaGetSymbolAddress((void**)&pH1l, gH1_lo);
    cudaGetSymbolAddress((void**)&pH2h, gH2_hi);
    cudaGetSymbolAddress((void**)&pH2l, gH2_lo);
    cudaGetSymbolAddress((void**)&pBiasH, gBiasH);
    cudaGetSymbolAddress((void**)&pComb, g_comb);

    cudaFuncSetAttribute(hgemm, cudaFuncAttributeMaxDynamicSharedMemorySize, SMEM_GEMM);
    cudaFuncSetAttribute(class_nms, cudaFuncAttributeMaxDynamicSharedMemorySize, CSMEM);

    // pre-pass: split into fp16 hi/lo
    split_X<<<(N_ROIS * IN_F / 4 + 255) / 256, 256>>>(X);
    tsplitW<<<dim3(IN_F / 32, REP / 32), dim3(32, 8)>>>(W1, pW1h, pW1l, IN_F, REP);
    tsplitW<<<dim3(REP / 32, REP / 32), dim3(32, 8)>>>(W2, pW2h, pW2l, REP, REP);
    build_head<<<dim3(NHEAD, REP / 256), 256>>>(Wc, Wr);
    build_bias<<<(NHEAD + 255) / 256, 256>>>(bc, br);

    // GEMM1: h1 = relu(X @ W1 + b1)
    hgemm<<<dim3(REP / 128, MPAD / 128), 256, SMEM_GEMM>>>(
        pAh, pAl, pW1h, pW1l, b1, IN_F, N_ROIS, 1, nullptr, 0, pH1h, pH1l, REP);
    // GEMM2: h2 = relu(h1 @ W2 + b2)
    hgemm<<<dim3(REP / 128, MPAD / 128), 256, SMEM_GEMM>>>(
        pH1h, pH1l, pW2h, pW2l, b2, REP, N_ROIS, 1, nullptr, 0, pH2h, pH2l, REP);
    // heads: comb = h2 @ [Wc|pad|Wr] + bias
    hgemm<<<dim3(NHEAD / 128, MPAD / 128), 256, SMEM_GEMM>>>(
        pH2h, pH2l, pWhh, pWhl, pBiasH, REP, N_ROIS, 0, pComb, NHEAD, nullptr, nullptr, 0);

    softmax_kernel<<<N_ROIS, 32>>>();
    class_nms<<<NC1, 256, CSMEM>>>(P, imh, imw);
    final_select<<<1, 128>>>(P, imh, imw, (float*)d_out, out_size);
}

// round 16
// speedup vs baseline: 1.3641x; 1.2887x over previous
#include <cuda_runtime.h>
#include <cuda_fp16.h>
#include <math.h>
#include <stdint.h>

#define N_ROIS 2000
#define MPAD   2048
#define IN_F   12544
#define REP    1024
#define NHEAD  512
#define NCLS   91
#define NC1    90
#define NPAD   2048
#define BBOX_CLIP_F 4.135166556742356f
#define MAXDET 100
#define KSPLIT 8
#define KCHUNK (IN_F / KSPLIT)    // 1568

// ======================= static scratch (no allocs) =======================
__device__ float gWhf[REP * NHEAD];
__device__ float gBiasH[NHEAD];
__device__ float gPart[KSPLIT * MPAD * REP];   // GEMM1 split-K partials (64MB)
__device__ float gH1f[MPAD * REP];
__device__ float gH2f[MPAD * REP];
__device__ float g_comb[N_ROIS * NHEAD];
__device__ float g_scores[N_ROIS * NCLS];
__device__ unsigned long long g_surv[NC1 * MAXDET];
__device__ int g_snum[NC1];

// ======================= helpers =======================
__device__ __forceinline__ uint32_t s2u(const void* p) {
    uint32_t a;
    asm("{ .reg .u64 t; cvta.to.shared.u64 t, %1; cvt.u32.u64 %0, t; }" : "=r"(a) : "l"(p));
    return a;
}
__device__ __forceinline__ void ldm4(uint32_t* r, uint32_t addr) {
    asm volatile("ldmatrix.sync.aligned.m8n8.x4.shared.b16 {%0,%1,%2,%3}, [%4];"
                 : "=r"(r[0]), "=r"(r[1]), "=r"(r[2]), "=r"(r[3]) : "r"(addr));
}
__device__ __forceinline__ void ldm4t(uint32_t* r, uint32_t addr) {
    asm volatile("ldmatrix.sync.aligned.m8n8.x4.trans.shared.b16 {%0,%1,%2,%3}, [%4];"
                 : "=r"(r[0]), "=r"(r[1]), "=r"(r[2]), "=r"(r[3]) : "r"(addr));
}
__device__ __forceinline__ void mma_f16(float* d, const uint32_t* a, const uint32_t* b) {
    asm volatile(
        "mma.sync.aligned.m16n8k16.row.col.f32.f16.f16.f32 "
        "{%0,%1,%2,%3}, {%4,%5,%6,%7}, {%8,%9}, {%0,%1,%2,%3};"
        : "+f"(d[0]), "+f"(d[1]), "+f"(d[2]), "+f"(d[3])
        : "r"(a[0]), "r"(a[1]), "r"(a[2]), "r"(a[3]), "r"(b[0]), "r"(b[1]));
}
__device__ __forceinline__ void split2u(float x, __half& h, __half& l) {
    h = __float2half_rn(x);
    l = __float2half_rn(x - __half2float(h));
}
__device__ __forceinline__ uint32_t pack2(__half a, __half b) {
    __half2 t; t.x = a; t.y = b;
    return *reinterpret_cast<uint32_t*>(&t);
}
__device__ __forceinline__ void decode_one(
    int n, int c, const float* __restrict__ P, float Wim, float Him,
    float& x1, float& y1, float& x2, float& y2)
{
    const float4 p = *reinterpret_cast<const float4*>(&P[n * 4]);
    const float pw = p.z - p.x;
    const float ph = p.w - p.y;
    const float pcx = p.x + 0.5f * pw;
    const float pcy = p.y + 0.5f * ph;
    const float4 r = *reinterpret_cast<const float4*>(&g_comb[(size_t)n * NHEAD + 92 + c * 4]);
    const float dx = r.x / 10.0f;
    const float dy = r.y / 10.0f;
    const float dw = fminf(r.z / 5.0f, BBOX_CLIP_F);
    const float dh = fminf(r.w / 5.0f, BBOX_CLIP_F);
    const float cx = dx * pw + pcx;
    const float cy = dy * ph + pcy;
    const float w = expf(dw) * pw;
    const float hh = expf(dh) * ph;
    x1 = fminf(fmaxf(cx - 0.5f * w, 0.f), Wim);
    y1 = fminf(fmaxf(cy - 0.5f * hh, 0.f), Him);
    x2 = fminf(fmaxf(cx + 0.5f * w, 0.f), Wim);
    y2 = fminf(fmaxf(cy + 0.5f * hh, 0.f), Him);
}

// ======================= tiny pre-pass =======================
__global__ void build_headW(const float* __restrict__ Wc, const float* __restrict__ Wr) {
    const int idx = blockIdx.x * 256 + threadIdx.x;
    const int k = idx >> 9;
    const int n = idx & (NHEAD - 1);
    float v = 0.f;
    if (n < NCLS) v = Wc[(size_t)k * NCLS + n];
    else if (n >= 92 && n < 92 + 4 * NCLS) v = Wr[(size_t)k * (4 * NCLS) + (n - 92)];
    gWhf[idx] = v;
}
__global__ void build_bias(const float* __restrict__ bc, const float* __restrict__ br) {
    const int c = blockIdx.x * 256 + threadIdx.x;
    if (c >= NHEAD) return;
    float v = 0.f;
    if (c < NCLS) v = bc[c];
    else if (c >= 92 && c < 92 + 4 * NCLS) v = br[c - 92];
    gBiasH[c] = v;
}

// ======================= fused-split HMMA GEMM (R9 core) =======================
// C = A[M,K_total] @ B[K_total,N] slice; in-kernel fp16 2-way split, one fp32 acc.
// mode: 0 = C + bias; 1 = C + bias + relu; 2 = raw split-K partial (no bias),
//       C indexed by blockIdx.z (kbeg = blockIdx.z * K).
template <int BN>
__global__ void __launch_bounds__(256, 1) hgemmF(
    const float* __restrict__ A, const float* __restrict__ B,
    const float* __restrict__ bias, int K, int lda, int ldb,
    int Mreal, int mode, float* __restrict__ C, int ldc)
{
    constexpr int ROWB  = BN * 2;
    constexpr int BTILE = 32 * ROWB;
    constexpr int STG   = 16384 + 2 * BTILE;
    constexpr int BJ    = (BN == 128) ? 4 : 2;
    constexpr int NWN   = BN / 32;
    constexpr int MF    = BN / 32;

    extern __shared__ __align__(16) char smem[];
    const uint32_t sb = s2u(smem);
    const int tid = threadIdx.x;
    const int lane = tid & 31, wid = tid >> 5;
    const int wn = wid % NWN, wm = wid / NWN;
    const int wmbase = wm * (MF * 16);
    const int bm = blockIdx.y * 128, bn = blockIdx.x * BN;
    const int kbeg = (mode == 2) ? (int)blockIdx.z * K : 0;
    float* Cz = (mode == 2) ? (C + (size_t)blockIdx.z * MPAD * REP) : C;
    const int niter = K >> 5;

    float acc[MF][4][4];
#pragma unroll
    for (int m = 0; m < MF; ++m)
#pragma unroll
        for (int n = 0; n < 4; ++n)
#pragma unroll
            for (int e = 0; e < 4; ++e) acc[m][n][e] = 0.f;

    float4 aS[4];
    float4 bS[BJ];
    const int r0 = tid >> 3, seg = tid & 7;

    auto ldgA = [&](int i) {
        const int k0 = kbeg + i * 32;
#pragma unroll
        for (int j = 0; j < 4; ++j) {
            const int gr = bm + r0 + 32 * j;
            if (gr < Mreal) aS[j] = *(const float4*)(A + (size_t)gr * lda + k0 + seg * 4);
            else aS[j] = make_float4(0.f, 0.f, 0.f, 0.f);
        }
    };
    auto ldgB = [&](int i) {
        const int k0 = kbeg + i * 32;
#pragma unroll
        for (int j = 0; j < BJ; ++j) {
            const int nf = seg * 4 + j * 32;
            bS[j] = *(const float4*)(B + (size_t)(k0 + r0) * ldb + bn + nf);
        }
    };
    auto stsStage = [&](int i) {
        char* st = smem + (size_t)(i % 3) * STG;
#pragma unroll
        for (int j = 0; j < 4; ++j) {
            const int row = r0 + 32 * j;
            __half h0, l0, h1, l1, h2, l2, h3, l3;
            split2u(aS[j].x, h0, l0); split2u(aS[j].y, h1, l1);
            split2u(aS[j].z, h2, l2); split2u(aS[j].w, h3, l3);
            uint32_t relh = (uint32_t)(row * 128 + seg * 8);
            relh ^= (relh >> 3) & 0x70;
            uint32_t rell = (uint32_t)(row * 128 + 64 + seg * 8);
            rell ^= (rell >> 3) & 0x70;
            uint2 vh; vh.x = pack2(h0, h1); vh.y = pack2(h2, h3);
            uint2 vl; vl.x = pack2(l0, l1); vl.y = pack2(l2, l3);
            *(uint2*)(st + relh) = vh;
            *(uint2*)(st + rell) = vl;
        }
#pragma unroll
        for (int j = 0; j < BJ; ++j) {
            const int nf = seg * 4 + j * 32;
            __half h0, l0, h1, l1, h2, l2, h3, l3;
            split2u(bS[j].x, h0, l0); split2u(bS[j].y, h1, l1);
            split2u(bS[j].z, h2, l2); split2u(bS[j].w, h3, l3);
            uint32_t rel = (uint32_t)(r0 * ROWB + nf * 2);
            if (BN == 128) rel ^= ((rel >> 8) & 7) << 4;
            else           rel ^= ((rel >> 7) & 7) << 4;
            uint2 vh; vh.x = pack2(h0, h1); vh.y = pack2(h2, h3);
            uint2 vl; vl.x = pack2(l0, l1); vl.y = pack2(l2, l3);
            *(uint2*)(st + 16384 + rel) = vh;
            *(uint2*)(st + 16384 + BTILE + rel) = vl;
        }
    };
    auto compute = [&](int i) {
        const uint32_t ab = sb + (uint32_t)(i % 3) * STG;
        const uint32_t bb = ab + 16384;
#pragma unroll
        for (int kk = 0; kk < 2; ++kk) {
            uint32_t Af[MF][4], Lf[MF][4], Bf[4][2], Mf[4][2];
#pragma unroll
            for (int m = 0; m < MF; ++m) {
                const int row = wmbase + m * 16 + (lane & 15);
                const int colb = kk * 32 + ((lane >> 4) << 4);
                uint32_t rr1 = (uint32_t)(row * 128 + colb);
                uint32_t rr2 = (uint32_t)(row * 128 + 64 + colb);
                rr1 ^= (rr1 >> 3) & 0x70;
                rr2 ^= (rr2 >> 3) & 0x70;
                ldm4(Af[m], ab + rr1);
                ldm4(Lf[m], ab + rr2);
            }
#pragma unroll
            for (int p = 0; p < 2; ++p) {
                const int grp = lane >> 3, kr = lane & 7;
                const int kx = kk * 16 + (grp & 1) * 8 + kr;
                const int nb = wn * 32 + p * 16 + (grp >> 1) * 8;
                uint32_t rel = (uint32_t)(kx * ROWB + nb * 2);
                if (BN == 128) rel ^= ((rel >> 8) & 7) << 4;
                else           rel ^= ((rel >> 7) & 7) << 4;
                uint32_t t[4];
                ldm4t(t, bb + rel);
                Bf[2 * p][0] = t[0]; Bf[2 * p][1] = t[1];
                Bf[2 * p + 1][0] = t[2]; Bf[2 * p + 1][1] = t[3];
                ldm4t(t, bb + BTILE + rel);
                Mf[2 * p][0] = t[0]; Mf[2 * p][1] = t[1];
                Mf[2 * p + 1][0] = t[2]; Mf[2 * p + 1][1] = t[3];
            }
#pragma unroll
            for (int m = 0; m < MF; ++m)
#pragma unroll
                for (int n = 0; n < 4; ++n) {
                    mma_f16(acc[m][n], Af[m], Bf[n]);
                    mma_f16(acc[m][n], Af[m], Mf[n]);
                    mma_f16(acc[m][n], Lf[m], Bf[n]);
                }
        }
    };

    ldgA(0); ldgB(0);
    stsStage(0);
    if (niter > 1) { ldgA(1); ldgB(1); }
    __syncthreads();
    for (int i = 0; i < niter; ++i) {
        if (i + 1 < niter) stsStage(i + 1);
        if (i + 2 < niter) { ldgA(i + 2); ldgB(i + 2); }
        __syncthreads();
        compute(i);
    }

    const int rb = bm + wmbase + (lane >> 2);
    const int cb = bn + wn * 32 + 2 * (lane & 3);
#pragma unroll
    for (int m = 0; m < MF; ++m) {
#pragma unroll
        for (int n = 0; n < 4; ++n) {
            const int cc = cb + n * 8;
            float2 bi = make_float2(0.f, 0.f);
            if (mode != 2) bi = *(const float2*)&bias[cc];
#pragma unroll
            for (int hf = 0; hf < 2; ++hf) {
                const int r = rb + m * 16 + hf * 8;
                if (r < Mreal) {
                    float v0 = acc[m][n][2 * hf + 0] + bi.x;
                    float v1 = acc[m][n][2 * hf + 1] + bi.y;
                    if (mode == 1) { v0 = fmaxf(v0, 0.f); v1 = fmaxf(v1, 0.f); }
                    float2 o; o.x = v0; o.y = v1;
                    *(float2*)&Cz[(size_t)r * ldc + cc] = o;
                }
            }
        }
    }
}

// reduce KSPLIT partials + bias + relu -> gH1f
__global__ void reduce_bias_relu(const float* __restrict__ b1) {
    const int idx = blockIdx.x * 256 + threadIdx.x;
    if (idx >= N_ROIS * REP / 4) return;
    const size_t e = (size_t)idx * 4;
    const int col = (int)(e & (REP - 1));
    float4 s = *(const float4*)(gPart + e);
#pragma unroll
    for (int z = 1; z < KSPLIT; ++z) {
        const float4 p = *(const float4*)(gPart + (size_t)z * MPAD * REP + e);
        s.x += p.x; s.y += p.y; s.z += p.z; s.w += p.w;
    }
    const float4 bb = *(const float4*)(b1 + col);
    float4 o;
    o.x = fmaxf(s.x + bb.x, 0.f);
    o.y = fmaxf(s.y + bb.y, 0.f);
    o.z = fmaxf(s.z + bb.z, 0.f);
    o.w = fmaxf(s.w + bb.w, 0.f);
    *(float4*)(gH1f + e) = o;
}

// ======================= softmax =======================
__global__ void softmax_kernel() {
    const int n = blockIdx.x;
    const int lane = threadIdx.x;
    float v[3];
    float mx = -3.4e38f;
#pragma unroll
    for (int t = 0; t < 3; ++t) {
        const int i = lane + 32 * t;
        v[t] = (i < NCLS) ? g_comb[(size_t)n * NHEAD + i] : -3.4e38f;
        mx = fmaxf(mx, v[t]);
    }
#pragma unroll
    for (int s = 16; s > 0; s >>= 1) mx = fmaxf(mx, __shfl_xor_sync(0xffffffffu, mx, s));
    float sum = 0.f;
#pragma unroll
    for (int t = 0; t < 3; ++t) {
        const int i = lane + 32 * t;
        if (i < NCLS) { v[t] = expf(v[t] - mx); sum += v[t]; }
    }
#pragma unroll
    for (int s = 16; s > 0; s >>= 1) sum += __shfl_xor_sync(0xffffffffu, sum, s);
#pragma unroll
    for (int t = 0; t < 3; ++t) {
        const int i = lane + 32 * t;
        if (i < NCLS) g_scores[n * NCLS + i] = v[t] / sum;
    }
}

// ======================= per-class NMS (512 thr, compact + sized bitonic) =======================
#define CSMEM (4 * NPAD * 4 + NPAD * 8 + NPAD)

__global__ void __launch_bounds__(512) class_nms(
    const float* __restrict__ P, const int* __restrict__ imh, const int* __restrict__ imw)
{
    extern __shared__ __align__(16) char smemraw[];
    float* sx1 = (float*)smemraw;
    float* sy1 = sx1 + NPAD;
    float* sx2 = sy1 + NPAD;
    float* sy2 = sx2 + NPAD;
    unsigned long long* keys = (unsigned long long*)(sy2 + NPAD);
    char* alive = (char*)(keys + NPAD);
    __shared__ int s_cnt;
    __shared__ int s_nsurv;

    const int tid = threadIdx.x;
    const int lane = tid & 31;
    const int cls = blockIdx.x;
    const int c = cls + 1;
    const float Wim = (float)(*imw);
    const float Him = (float)(*imh);
    const float offv = (float)c * (fmaxf(Wim, Him) + 1.0f);

    if (tid == 0) { s_cnt = 0; s_nsurv = 0; }
    for (int i = tid; i < NPAD; i += 512) { keys[i] = 0ull; alive[i] = 1; }
    __syncthreads();

    // decode + validate + compact (order arbitrary; full sort restores determinism)
    for (int n0 = 0; n0 < NPAD; n0 += 512) {
        const int n = n0 + tid;
        unsigned long long key = 0ull;
        if (n < N_ROIS) {
            float x1, y1, x2, y2;
            decode_one(n, c, P, Wim, Him, x1, y1, x2, y2);
            const float s = g_scores[n * NCLS + c];
            if (s > 0.05f && (x2 - x1) >= 0.01f && (y2 - y1) >= 0.01f) {
                sx1[n] = x1 + offv;
                sy1[n] = y1 + offv;
                sx2[n] = x2 + offv;
                sy2[n] = y2 + offv;
                key = ((unsigned long long)__float_as_uint(s) << 32)
                    | (unsigned long long)(0xFFFFFFFFu - (unsigned)n);
            }
        }
        const unsigned ball = __ballot_sync(0xffffffffu, key != 0ull);
        const int wpre = __popc(ball & ((1u << lane) - 1u));
        const int wcnt = __popc(ball);
        int base = 0;
        if (lane == 0 && wcnt) base = atomicAdd(&s_cnt, wcnt);
        base = __shfl_sync(0xffffffffu, base, 0);
        if (key != 0ull) keys[base + wpre] = key;
    }
    __syncthreads();
    const int cnt = s_cnt;
    if (cnt == 0) { if (tid == 0) g_snum[cls] = 0; return; }

    int S = 32;
    while (S < cnt) S <<= 1;

    // bitonic sort descending over [0, S)
    for (int k = 2; k <= S; k <<= 1) {
        for (int j = k >> 1; j > 0; j >>= 1) {
            for (int i = tid; i < S; i += 512) {
                const int l = i ^ j;
                if (l > i) {
                    const unsigned long long a = keys[i], b = keys[l];
                    const bool up = ((i & k) == 0);
                    if (up ? (a < b) : (a > b)) { keys[i] = b; keys[l] = a; }
                }
            }
            __syncthreads();
        }
    }

    // greedy NMS over compacted, sorted keys
    for (int pos = 0; pos < cnt; ++pos) {
        const unsigned long long k = keys[pos];
        if (k == 0ull) break;
        if (!alive[pos]) continue;
        if (s_nsurv >= MAXDET) break;
        const int ni = (int)(0xFFFFFFFFu - (unsigned)(k & 0xFFFFFFFFull));
        const float bx1 = sx1[ni], by1 = sy1[ni], bx2 = sx2[ni], by2 = sy2[ni];
        const float ai = (bx2 - bx1) * (by2 - by1);
        if (tid == 0) {
            const unsigned flat = (unsigned)(ni * NC1 + cls);
            g_surv[cls * MAXDET + s_nsurv] =
                (k & 0xFFFFFFFF00000000ull) | (unsigned long long)(0xFFFFFFFFu - flat);
            s_nsurv++;
        }
        for (int j = pos + 1 + tid; j < cnt; j += 512) {
            if (!alive[j]) continue;
            const unsigned long long k2 = keys[j];
            if (k2 == 0ull) continue;
            const int nj = (int)(0xFFFFFFFFu - (unsigned)(k2 & 0xFFFFFFFFull));
            const float xx1 = fmaxf(bx1, sx1[nj]);
            const float yy1 = fmaxf(by1, sy1[nj]);
            const float xx2 = fminf(bx2, sx2[nj]);
            const float yy2 = fminf(by2, sy2[nj]);
            const float inter = fmaxf(xx2 - xx1, 0.f) * fmaxf(yy2 - yy1, 0.f);
            const float aj = (sx2[nj] - sx1[nj]) * (sy2[nj] - sy1[nj]);
            const float iou = inter / (ai + aj - inter + 1e-9f);
            if (iou > 0.5f) alive[j] = 0;
        }
        __syncthreads();
    }
    __syncthreads();
    if (tid == 0) g_snum[cls] = s_nsurv;
}

// ======================= merge + output (warp-shfl argmax) =======================
__device__ __forceinline__ unsigned long long shflmax(unsigned long long v) {
#pragma unroll
    for (int s = 16; s > 0; s >>= 1) {
        const unsigned long long o = __shfl_xor_sync(0xffffffffu, v, s);
        if (o > v) v = o;
    }
    return v;
}

__global__ void __launch_bounds__(128) final_select(
    const float* __restrict__ P, const int* __restrict__ imh, const int* __restrict__ imw,
    float* __restrict__ out, int out_size)
{
    __shared__ unsigned long long warpmax[4];
    __shared__ unsigned long long s_best;
    __shared__ int heads[NC1];
    __shared__ int cnts[NC1];
    __shared__ int keep[MAXDET];
    __shared__ int s_w;

    const int tid = threadIdx.x;
    const int lane = tid & 31, wid = tid >> 5;
    if (tid < NC1) { heads[tid] = 0; cnts[tid] = g_snum[tid]; }
    if (tid < MAXDET) keep[tid] = -1;
    __syncthreads();

    for (int it = 0; it < MAXDET; ++it) {
        unsigned long long cand = 0ull;
        if (tid < NC1 && heads[tid] < cnts[tid])
            cand = g_surv[tid * MAXDET + heads[tid]];
        unsigned long long v = shflmax(cand);
        if (lane == 0) warpmax[wid] = v;
        __syncthreads();
        if (wid == 0) {
            unsigned long long w = (lane < 4) ? warpmax[lane] : 0ull;
#pragma unroll
            for (int s = 2; s > 0; s >>= 1) {
                const unsigned long long o = __shfl_xor_sync(0xffffffffu, w, s);
                if (o > w) w = o;
            }
            if (lane == 0) s_best = w;
        }
        __syncthreads();
        const unsigned long long best = s_best;
        if (best == 0ull) break;
        if (tid < NC1 && cand == best) s_w = tid;
        __syncthreads();
        if (tid == 0) {
            heads[s_w]++;
            keep[it] = (int)(0xFFFFFFFFu - (unsigned)(best & 0xFFFFFFFFull));
        }
        __syncthreads();
    }

    if (tid < MAXDET) {
        const int k = keep[tid];
        float b0 = 0, b1 = 0, b2 = 0, b3 = 0, s = 0, l = 0;
        if (k >= 0) {
            const int n = k / NC1;
            const int c = k % NC1 + 1;
            const float Wim = (float)(*imw);
            const float Him = (float)(*imh);
            float x1, y1, x2, y2;
            decode_one(n, c, P, Wim, Him, x1, y1, x2, y2);
            b0 = x1; b1 = y1; b2 = x2; b3 = y2;
            s = g_scores[n * NCLS + c];
            l = (float)c;
        }
        if (tid * 4 + 3 < out_size) {
            out[tid * 4 + 0] = b0;
            out[tid * 4 + 1] = b1;
            out[tid * 4 + 2] = b2;
            out[tid * 4 + 3] = b3;
        }
        if (4 * MAXDET + tid < out_size) out[4 * MAXDET + tid] = s;
        if (5 * MAXDET + tid < out_size) out[5 * MAXDET + tid] = l;
    }
}

// ======================= launch =======================
extern "C" void kernel_launch(void* const* d_in, const int* in_sizes, int n_in,
                              void* d_out, int out_size) {
    const float* X  = (const float*)d_in[0];
    const float* P  = (const float*)d_in[1];
    const float* W1 = (const float*)d_in[2];
    const float* b1 = (const float*)d_in[3];
    const float* W2 = (const float*)d_in[4];
    const float* b2 = (const float*)d_in[5];
    const float* Wc = (const float*)d_in[6];
    const float* bc = (const float*)d_in[7];
    const float* Wr = (const float*)d_in[8];
    const float* br = (const float*)d_in[9];
    const int* imh  = (const int*)d_in[10];
    const int* imw  = (const int*)d_in[11];

    float *pWh, *pBiasH, *pPart, *pH1, *pH2, *pComb;
    cudaGetSymbolAddress((void**)&pWh, gWhf);
    cudaGetSymbolAddress((void**)&pBiasH, gBiasH);
    cudaGetSymbolAddress((void**)&pPart, gPart);
    cudaGetSymbolAddress((void**)&pH1, gH1f);
    cudaGetSymbolAddress((void**)&pH2, gH2f);
    cudaGetSymbolAddress((void**)&pComb, g_comb);

    const int SMEM128 = 3 * (16384 + 2 * (32 * 256));   // 98304
    const int SMEM64  = 3 * (16384 + 2 * (32 * 128));   // 73728
    cudaFuncSetAttribute(hgemmF<128>, cudaFuncAttributeMaxDynamicSharedMemorySize, SMEM128);
    cudaFuncSetAttribute(hgemmF<64>,  cudaFuncAttributeMaxDynamicSharedMemorySize, SMEM64);
    cudaFuncSetAttribute(class_nms, cudaFuncAttributeMaxDynamicSharedMemorySize, CSMEM);

    build_headW<<<REP * NHEAD / 256, 256>>>(Wc, Wr);
    build_bias<<<(NHEAD + 255) / 256, 256>>>(bc, br);

    // GEMM1 (split-K=8): partials = X @ W1 slices; then h1 = relu(sum + b1)
    hgemmF<128><<<dim3(REP / 128, MPAD / 128, KSPLIT), 256, SMEM128>>>(
        X, W1, nullptr, KCHUNK, IN_F, REP, N_ROIS, 2, pPart, REP);
    reduce_bias_relu<<<(N_ROIS * REP / 4 + 255) / 256, 256>>>(b1);

    // GEMM2: h2 = relu(h1 @ W2 + b2)
    hgemmF<128><<<dim3(REP / 128, MPAD / 128), 256, SMEM128>>>(
        pH1, W2, b2, REP, REP, REP, N_ROIS, 1, pH2, REP);
    // heads: comb = h2 @ Wh + biasH
    hgemmF<64><<<dim3(NHEAD / 64, MPAD / 128), 256, SMEM64>>>(
        pH2, pWh, pBiasH, REP, REP, NHEAD, N_ROIS, 0, pComb, NHEAD);

    softmax_kernel<<<N_ROIS, 32>>>();
    class_nms<<<NC1, 512, CSMEM>>>(P, imh, imw);
    final_select<<<1, 128>>>(P, imh, imw, (float*)d_out, out_size);
}